// round 4
// baseline (speedup 1.0000x reference)
#include <cuda_runtime.h>
#include <cuda_bf16.h>
#include <math.h>

#define NN 32768
#define EE 262144
#define FF 64
#define ZZ 10
#define NBB 8
#define LL 2
#define HH 16
#define EPS_SC 0.24253562503633297f  /* 1/sqrt(17) */

// ---------------- scratch (static device globals; no allocation) -------------
__device__ float g_s0[NN * FF];
__device__ float g_s1[NN * FF];
__device__ float g_v0[NN * 3 * FF];          // only layer-0 output v lives here
__device__ float g_aggs[NN * FF];
__device__ float g_aggv[NN * 3 * FF];
__device__ float g_rbf[EE * NBB];
__device__ float g_Y[EE * 3];

// ---------------- zero the aggregation buffers --------------------------------
__global__ void zero_agg_kernel()
{
    int i = blockIdx.x * blockDim.x + threadIdx.x;      // (N*F + N*3*F)/4 float4
    float4 z = make_float4(0.f, 0.f, 0.f, 0.f);
    if (i < (NN * FF) / 4)      reinterpret_cast<float4*>(g_aggs)[i] = z;
    if (i < (NN * 3 * FF) / 4)  reinterpret_cast<float4*>(g_aggv)[i] = z;
}

// ---------------- per-edge radial basis + unit vector (layer invariant) ------
__global__ void precompute_kernel(const float* __restrict__ vectors)
{
    int e = blockIdx.x * blockDim.x + threadIdx.x;
    if (e >= EE) return;
    float x = vectors[e * 3 + 0];
    float y = vectors[e * 3 + 1];
    float z = vectors[e * 3 + 2];
    float r2 = x * x + y * y + z * z + 1e-12f;
    float r  = sqrtf(r2);
    float inv = 1.0f / r;
    g_Y[e * 3 + 0] = x * inv;
    g_Y[e * 3 + 1] = y * inv;
    g_Y[e * 3 + 2] = z * inv;
    float rc = fmaxf(r, 1e-6f);
    float r6 = r2 * r2 * r2;
    float env = 1.0f - 28.0f * r6 + 48.0f * r6 * r - 21.0f * r6 * r2;  // p=6 envelope
    if (r >= 1.0f) env = 0.0f;
    float kk = env * 1.4142135623730951f / rc;
    float pr = 3.14159265358979323846f * rc;
#pragma unroll
    for (int n = 1; n <= NBB; n++)
        g_rbf[e * NBB + (n - 1)] = kk * sinf((float)n * pr);
}

// ---------------- node embedding init ----------------------------------------
__global__ void init_kernel(const float* __restrict__ embed_s,
                            const int* __restrict__ spec)
{
    int i = blockIdx.x * blockDim.x + threadIdx.x;  // N*F threads
    int n = i >> 6;
    int f = i & 63;
    g_s0[i] = embed_s[spec[n] * FF + f];
}

// ---------------- edge kernel: CG tensor product + scatter-add ----------------
// v layout: [n][k][f]   (f contiguous, k in {0,1,2})
template <int ITER>
__global__ void __launch_bounds__(256)
edge_kernel(const float* __restrict__ Wr_i,  // [8,320] for this layer
            const int* __restrict__ senders, const int* __restrict__ receivers)
{
    __shared__ float sWr[NBB * 5 * FF];  // 2560 floats = 10 KB
    for (int i = threadIdx.x; i < NBB * 5 * FF; i += blockDim.x) sWr[i] = Wr_i[i];
    __syncthreads();

    const float* s = (ITER == 0) ? g_s0 : g_s1;
    const float* v = g_v0;   // only valid/used when ITER==1

    int grp = threadIdx.x >> 6;   // 4 edge-groups per block
    int f   = threadIdx.x & 63;
    int stride = gridDim.x * 4;

    for (int e = blockIdx.x * 4 + grp; e < EE; e += stride) {
        int snd = senders[e];
        int rcv = receivers[e];
        float y0 = g_Y[e * 3 + 0], y1 = g_Y[e * 3 + 1], y2 = g_Y[e * 3 + 2];

        float w0 = 0.f, w1 = 0.f, w2 = 0.f, w3 = 0.f, w4 = 0.f;
#pragma unroll
        for (int b = 0; b < NBB; b++) {
            float rb = g_rbf[e * NBB + b];
            const float* wr = &sWr[b * 320];
            w0 = fmaf(rb, wr[f],       w0);
            w1 = fmaf(rb, wr[64 + f],  w1);
            w2 = fmaf(rb, wr[128 + f], w2);
            w3 = fmaf(rb, wr[192 + f], w3);
            w4 = fmaf(rb, wr[256 + f], w4);
        }

        float ss = s[snd * FF + f];
        float m0, m10, m11, m12;
        if (ITER == 0) {
            // v == 0 on the first interaction
            m0  = w0 * ss;
            float w2s = w2 * ss;
            m10 = w2s * y0; m11 = w2s * y1; m12 = w2s * y2;
        } else {
            const float* vb = v + snd * 3 * FF;
            float vx = vb[f], vy = vb[64 + f], vz = vb[128 + f];
            float dot = vx * y0 + vy * y1 + vz * y2;
            m0 = fmaf(w1, dot, w0 * ss);
            float c0 = vy * y2 - vz * y1;
            float c1 = vz * y0 - vx * y2;
            float c2 = vx * y1 - vy * y0;
            float w2s = w2 * ss;
            m10 = fmaf(w2s, y0, fmaf(w3, vx, w4 * c0));
            m11 = fmaf(w2s, y1, fmaf(w3, vy, w4 * c1));
            m12 = fmaf(w2s, y2, fmaf(w3, vz, w4 * c2));
        }
        atomicAdd(&g_aggs[rcv * FF + f], m0);
        float* av = g_aggv + rcv * 3 * FF;
        atomicAdd(&av[f],        m10);
        atomicAdd(&av[64 + f],   m11);
        atomicAdd(&av[128 + f],  m12);
    }
}

// ---------------- fused node kernel -------------------------------------------
// agg -> (Wls,Wlv) -> product basis -> (Wps,Wpv) (+ per-species skip) -> readout
#define SMEM_NODE ((16384 + 4 * 512) * 4)  /* 72 KB */

template <int ITER>
__global__ void __launch_bounds__(256)
node_kernel(const int* __restrict__ species,
            const float* __restrict__ Wls, const float* __restrict__ Wlv,
            const float* __restrict__ Wps, const float* __restrict__ Wpv,
            const float* __restrict__ skip_s, const float* __restrict__ skip_v,
            const float* __restrict__ pw,     // [Z,9,F] for this layer
            const float* __restrict__ Wread0, const float* __restrict__ Wr1a,
            const float* __restrict__ Wr1b,
            float* __restrict__ out)
{
    extern __shared__ float sm[];
    float* sWls = sm;
    float* sWlv = sm + 4096;
    float* sWps = sm + 8192;
    float* sWpv = sm + 12288;
    float* sStage = sm + 16384;  // 4 nodes x 512 floats

    for (int i = threadIdx.x; i < 4096; i += 256) {
        sWls[i] = Wls[i];
        sWlv[i] = Wlv[i];
        sWps[i] = Wps[i];
        sWpv[i] = Wpv[i];
    }
    __syncthreads();

    // ITER==0: inputs s=g_s0 (v is zero), outputs s1,v0.
    // ITER==1: inputs s=g_s1, v=g_v0; outputs dead (readout only).
    const float* s_in = (ITER == 0) ? g_s0 : g_s1;
    const float* v_in = g_v0;

    int r = threadIdx.x >> 6;   // node slot 0..3
    int g = threadIdx.x & 63;   // output feature
    float* stA  = sStage + r * 512;  // agg_s row / later ps
    float* stV  = stA + 64;          // agg_v rows (192) / later pv
    float* stS  = stA + 256;         // old s row (skip)
    float* stVi = stA + 320;         // old v rows (skip, 192)

    for (int chunk = 0; chunk < 8; chunk++) {
        int n = blockIdx.x * 32 + chunk * 4 + r;

        stA[g] = g_aggs[n * FF + g] * EPS_SC;
        {
            const float* av = g_aggv + n * 3 * FF;
            stV[g]        = av[g] * EPS_SC;
            stV[64 + g]   = av[64 + g] * EPS_SC;
            stV[128 + g]  = av[128 + g] * EPS_SC;
        }
        if (ITER > 0) {
            stS[g] = s_in[n * FF + g];
            const float* vb = v_in + n * 3 * FF;
            stVi[g]       = vb[g];
            stVi[64 + g]  = vb[64 + g];
            stVi[128 + g] = vb[128 + g];
        }
        __syncthreads();

        int spec = species[n];
        const float* sks = skip_s + spec * 4096;
        const float* skv = skip_v + spec * 4096;

        float s2 = 0.f, v20 = 0.f, v21 = 0.f, v22 = 0.f;
        float scs = 0.f, scv0 = 0.f, scv1 = 0.f, scv2 = 0.f;
#pragma unroll 8
        for (int f = 0; f < FF; f++) {
            int idx = f * 64 + g;
            float a = stA[f];
            s2 = fmaf(a, sWls[idx], s2);
            float wl = sWlv[idx];
            v20 = fmaf(stV[f],        wl, v20);
            v21 = fmaf(stV[64 + f],   wl, v21);
            v22 = fmaf(stV[128 + f],  wl, v22);
            if (ITER > 0) {
                scs = fmaf(stS[f], sks[idx], scs);
                float wv = skv[idx];
                scv0 = fmaf(stVi[f],       wv, scv0);
                scv1 = fmaf(stVi[64 + f],  wv, scv1);
                scv2 = fmaf(stVi[128 + f], wv, scv2);
            }
        }

        float vv = v20 * v20 + v21 * v21 + v22 * v22;
        const float* p = pw + spec * 9 * FF + g;
        float p0 = p[0], p1 = p[64], p2 = p[128], p3 = p[192], p4 = p[256];
        float p5 = p[320], p6 = p[384], p7 = p[448], p8 = p[512];
        float s2sq = s2 * s2;
        float psv = p0 * s2 + p1 * s2sq + p2 * vv + p3 * s2sq * s2 + p4 * s2 * vv;
        float pc  = p5 + p6 * s2 + p7 * s2sq + p8 * vv;

        __syncthreads();
        stA[g]       = psv;
        stV[g]       = pc * v20;
        stV[64 + g]  = pc * v21;
        stV[128 + g] = pc * v22;
        __syncthreads();

        float sn  = (ITER > 0) ? scs : 0.f;
        float vn0 = (ITER > 0) ? scv0 : 0.f;
        float vn1 = (ITER > 0) ? scv1 : 0.f;
        float vn2 = (ITER > 0) ? scv2 : 0.f;
#pragma unroll 8
        for (int f = 0; f < FF; f++) {
            int idx = f * 64 + g;
            sn = fmaf(stA[f], sWps[idx], sn);
            float wp = sWpv[idx];
            vn0 = fmaf(stV[f],       wp, vn0);
            vn1 = fmaf(stV[64 + f],  wp, vn1);
            vn2 = fmaf(stV[128 + f], wp, vn2);
        }

        if (ITER == 0) {
            // next layer needs these
            g_s1[n * FF + g] = sn;
            float* vo = g_v0 + n * 3 * FF;
            vo[g]        = vn0;
            vo[64 + g]   = vn1;
            vo[128 + g]  = vn2;
        }
        // ITER==1: s/v outputs are dead (final readout only) -> skip stores

        // ----- readout -----
        __syncthreads();
        if (ITER == 0) {
            stA[g] = sn * Wread0[g];
            __syncthreads();
            if (g == 0) {
                float t = 0.f;
                for (int j = 0; j < 64; j++) t += stA[j];
                out[n * LL + 0] = t;
            }
        } else {
            stA[g] = sn;
            __syncthreads();
            if (g < HH) {
                float h = 0.f;
#pragma unroll 8
                for (int f = 0; f < FF; f++) h = fmaf(stA[f], Wr1a[f * HH + g], h);
                h = h / (1.0f + expf(-h));  // silu
                stV[g] = h * Wr1b[g];
            }
            __syncthreads();
            if (g == 0) {
                float t = 0.f;
                for (int j = 0; j < HH; j++) t += stV[j];
                out[n * LL + 1] = t;
            }
        }
        __syncthreads();
    }
}

// ---------------- host launch -------------------------------------------------
extern "C" void kernel_launch(void* const* d_in, const int* in_sizes, int n_in,
                              void* d_out, int out_size)
{
    const float* vectors  = (const float*)d_in[0];
    const float* embed_s  = (const float*)d_in[1];
    const float* Wr       = (const float*)d_in[2];   // [2,8,320]
    const float* Wls      = (const float*)d_in[3];   // [2,64,64]
    const float* Wlv      = (const float*)d_in[4];
    const float* skip_s   = (const float*)d_in[5];   // [10,64,64]
    const float* skip_v   = (const float*)d_in[6];
    const float* pw       = (const float*)d_in[7];   // [2,10,9,64]
    const float* Wps      = (const float*)d_in[8];
    const float* Wpv      = (const float*)d_in[9];
    const float* Wread0   = (const float*)d_in[10];  // [64,1]
    const float* Wr1a     = (const float*)d_in[11];  // [64,16]
    const float* Wr1b     = (const float*)d_in[12];  // [16,1]
    const int*   senders  = (const int*)d_in[13];
    const int*   receivers= (const int*)d_in[14];
    const int*   species  = (const int*)d_in[15];
    float* out = (float*)d_out;

    static bool attr_done = false;
    if (!attr_done) {
        cudaFuncSetAttribute((const void*)node_kernel<0>,
                             cudaFuncAttributeMaxDynamicSharedMemorySize, SMEM_NODE);
        cudaFuncSetAttribute((const void*)node_kernel<1>,
                             cudaFuncAttributeMaxDynamicSharedMemorySize, SMEM_NODE);
        attr_done = true;
    }

    const int zthreads = 256;
    const int zblocks  = (NN * 3 * FF / 4 + zthreads - 1) / zthreads;

    precompute_kernel<<<EE / 256, 256>>>(vectors);
    init_kernel<<<(NN * FF) / 256, 256>>>(embed_s, species);

    // ---- layer 0 ----
    zero_agg_kernel<<<zblocks, zthreads>>>();
    edge_kernel<0><<<2048, 256>>>(Wr, senders, receivers);
    node_kernel<0><<<NN / 32, 256, SMEM_NODE>>>(
        species, Wls, Wlv, Wps, Wpv, skip_s, skip_v, pw,
        Wread0, Wr1a, Wr1b, out);

    // ---- layer 1 ----
    zero_agg_kernel<<<zblocks, zthreads>>>();
    edge_kernel<1><<<2048, 256>>>(Wr + NBB * 5 * FF, senders, receivers);
    node_kernel<1><<<NN / 32, 256, SMEM_NODE>>>(
        species,
        Wls + FF * FF, Wlv + FF * FF, Wps + FF * FF, Wpv + FF * FF,
        skip_s, skip_v, pw + ZZ * 9 * FF,
        Wread0, Wr1a, Wr1b, out);
}

// round 5
// speedup vs baseline: 1.1928x; 1.1928x over previous
#include <cuda_runtime.h>
#include <cuda_bf16.h>
#include <math.h>

#define NN 32768
#define EE 262144
#define FF 64
#define ZZ 10
#define NBB 8
#define LL 2
#define HH 16
#define EPS_SC 0.24253562503633297f  /* 1/sqrt(17) */

// ---------------- scratch (static device globals; no allocation) -------------
__device__ float  g_s0[NN * FF];
__device__ float  g_s1[NN * FF];
__device__ float  g_v0[NN * 3 * FF];            // [n][k][f], layer-0 output v
__device__ float4 g_agg[NN * FF];               // (s, vx, vy, vz) per (n,f)
__device__ float  g_rbf[EE * NBB];
__device__ float  g_Y[EE * 3];

// ---------------- zero the aggregation buffer ---------------------------------
__global__ void zero_agg_kernel()
{
    int i = blockIdx.x * blockDim.x + threadIdx.x;   // NN*FF float4 slots
    if (i < NN * FF) g_agg[i] = make_float4(0.f, 0.f, 0.f, 0.f);
}

// ---------------- per-edge radial basis + unit vector (layer invariant) ------
__global__ void precompute_kernel(const float* __restrict__ vectors)
{
    int e = blockIdx.x * blockDim.x + threadIdx.x;
    if (e >= EE) return;
    float x = vectors[e * 3 + 0];
    float y = vectors[e * 3 + 1];
    float z = vectors[e * 3 + 2];
    float r2 = x * x + y * y + z * z + 1e-12f;
    float r  = sqrtf(r2);
    float inv = 1.0f / r;
    g_Y[e * 3 + 0] = x * inv;
    g_Y[e * 3 + 1] = y * inv;
    g_Y[e * 3 + 2] = z * inv;
    float rc = fmaxf(r, 1e-6f);
    float r6 = r2 * r2 * r2;
    float env = 1.0f - 28.0f * r6 + 48.0f * r6 * r - 21.0f * r6 * r2;  // p=6 envelope
    if (r >= 1.0f) env = 0.0f;
    float kk = env * 1.4142135623730951f / rc;
    float pr = 3.14159265358979323846f * rc;
#pragma unroll
    for (int n = 1; n <= NBB; n++)
        g_rbf[e * NBB + (n - 1)] = kk * sinf((float)n * pr);
}

// ---------------- node embedding init ----------------------------------------
__global__ void init_kernel(const float* __restrict__ embed_s,
                            const int* __restrict__ spec)
{
    int i = blockIdx.x * blockDim.x + threadIdx.x;  // N*F threads
    int n = i >> 6;
    int f = i & 63;
    g_s0[i] = embed_s[spec[n] * FF + f];
}

// ---------------- edge kernel: CG tensor product + v4 scatter-add -------------
template <int ITER>
__global__ void __launch_bounds__(256)
edge_kernel(const float* __restrict__ Wr_i,  // [8,320] for this layer
            const int* __restrict__ senders, const int* __restrict__ receivers)
{
    __shared__ float sWr[NBB * 5 * FF];  // 2560 floats = 10 KB
    for (int i = threadIdx.x; i < NBB * 5 * FF; i += blockDim.x) sWr[i] = Wr_i[i];
    __syncthreads();

    const float* s = (ITER == 0) ? g_s0 : g_s1;
    const float* v = g_v0;   // only used when ITER==1

    int grp = threadIdx.x >> 6;   // 4 edge-groups per block
    int f   = threadIdx.x & 63;
    int stride = gridDim.x * 4;

    for (int e = blockIdx.x * 4 + grp; e < EE; e += stride) {
        int snd = senders[e];
        int rcv = receivers[e];
        float y0 = g_Y[e * 3 + 0], y1 = g_Y[e * 3 + 1], y2 = g_Y[e * 3 + 2];

        float w0 = 0.f, w1 = 0.f, w2 = 0.f, w3 = 0.f, w4 = 0.f;
#pragma unroll
        for (int b = 0; b < NBB; b++) {
            float rb = g_rbf[e * NBB + b];
            const float* wr = &sWr[b * 320];
            w0 = fmaf(rb, wr[f],       w0);
            w1 = fmaf(rb, wr[64 + f],  w1);
            w2 = fmaf(rb, wr[128 + f], w2);
            w3 = fmaf(rb, wr[192 + f], w3);
            w4 = fmaf(rb, wr[256 + f], w4);
        }

        float ss = s[snd * FF + f];
        float m0, m10, m11, m12;
        if (ITER == 0) {
            m0  = w0 * ss;
            float w2s = w2 * ss;
            m10 = w2s * y0; m11 = w2s * y1; m12 = w2s * y2;
        } else {
            const float* vb = v + snd * 3 * FF;
            float vx = vb[f], vy = vb[64 + f], vz = vb[128 + f];
            float dot = vx * y0 + vy * y1 + vz * y2;
            m0 = fmaf(w1, dot, w0 * ss);
            float c0 = vy * y2 - vz * y1;
            float c1 = vz * y0 - vx * y2;
            float c2 = vx * y1 - vy * y0;
            float w2s = w2 * ss;
            m10 = fmaf(w2s, y0, fmaf(w3, vx, w4 * c0));
            m11 = fmaf(w2s, y1, fmaf(w3, vy, w4 * c1));
            m12 = fmaf(w2s, y2, fmaf(w3, vz, w4 * c2));
        }
        float4* dst = &g_agg[rcv * FF + f];
        asm volatile("red.global.add.v4.f32 [%0], {%1, %2, %3, %4};"
                     :: "l"(dst), "f"(m0), "f"(m10), "f"(m11), "f"(m12)
                     : "memory");
    }
}

// ---------------- fused node kernel: one warp per node -------------------------
// agg -> (Wls,Wlv) -> product basis -> (Wps,Wpv) (+ per-species skip) -> readout
#define SMEM_NODE ((16384 + 8 * 512) * 4)   /* 80 KB */

template <int ITER>
__global__ void __launch_bounds__(256)
node_kernel(const int* __restrict__ species,
            const float* __restrict__ Wls, const float* __restrict__ Wlv,
            const float* __restrict__ Wps, const float* __restrict__ Wpv,
            const float* __restrict__ skip_s, const float* __restrict__ skip_v,
            const float* __restrict__ pw,     // [Z,9,F] for this layer
            const float* __restrict__ Wread0, const float* __restrict__ Wr1a,
            const float* __restrict__ Wr1b,
            float* __restrict__ out)
{
    extern __shared__ float sm[];
    float* sWls = sm;
    float* sWlv = sm + 4096;
    float* sWps = sm + 8192;
    float* sWpv = sm + 12288;
    float* sStage = sm + 16384;            // 8 warps x 512 floats

    for (int i = threadIdx.x; i < 4096; i += 256) {
        sWls[i] = Wls[i];
        sWlv[i] = Wlv[i];
        sWps[i] = Wps[i];
        sWpv[i] = Wpv[i];
    }
    __syncthreads();

    int wid = threadIdx.x >> 5;            // warp = node slot
    int g2  = threadIdx.x & 31;            // handles outputs 2*g2, 2*g2+1
    int go  = 2 * g2;

    float* stA  = sStage + wid * 512;      // 64:  agg_s / ps
    float* stV  = stA + 64;                // 192: agg_v / pv
    float* stS  = stA + 256;               // 64:  old s (skip input)
    float* stVi = stA + 320;               // 192: old v (skip input)

#pragma unroll 1
    for (int chunk = 0; chunk < 8; chunk++) {
        int n = blockIdx.x * 64 + chunk * 8 + wid;

        // ---- stage inputs (one LDG.128 per output pair) ----
        {
            float4 a0 = g_agg[n * FF + go];
            float4 a1 = g_agg[n * FF + go + 1];
            stA[go]        = a0.x * EPS_SC;  stA[go + 1]        = a1.x * EPS_SC;
            stV[go]        = a0.y * EPS_SC;  stV[go + 1]        = a1.y * EPS_SC;
            stV[64 + go]   = a0.z * EPS_SC;  stV[64 + go + 1]   = a1.z * EPS_SC;
            stV[128 + go]  = a0.w * EPS_SC;  stV[128 + go + 1]  = a1.w * EPS_SC;
        }
        if (ITER > 0) {
            float2 sv = *(const float2*)&g_s1[n * FF + go];
            stS[go] = sv.x; stS[go + 1] = sv.y;
            const float* vb = g_v0 + n * 3 * FF;
            float2 t;
            t = *(const float2*)&vb[go];        stVi[go] = t.x;        stVi[go + 1] = t.y;
            t = *(const float2*)&vb[64 + go];   stVi[64 + go] = t.x;   stVi[64 + go + 1] = t.y;
            t = *(const float2*)&vb[128 + go];  stVi[128 + go] = t.x;  stVi[128 + go + 1] = t.y;
        }
        __syncwarp();

        int spec = species[n];
        const float* sks = skip_s + spec * 4096;
        const float* skv = skip_v + spec * 4096;

        // ---- first matvec pair (+ skip matvecs) ----
        float s2a = 0.f, s2b = 0.f;
        float vxa = 0.f, vya = 0.f, vza = 0.f, vxb = 0.f, vyb = 0.f, vzb = 0.f;
        float sca = 0.f, scb = 0.f;
        float ka0 = 0.f, ka1 = 0.f, ka2 = 0.f, kb0 = 0.f, kb1 = 0.f, kb2 = 0.f;
#pragma unroll 8
        for (int f = 0; f < FF; f++) {
            float a  = stA[f];
            float wx = stV[f], wy = stV[64 + f], wz = stV[128 + f];
            float2 wls = *(const float2*)&sWls[f * 64 + go];
            float2 wlv = *(const float2*)&sWlv[f * 64 + go];
            s2a = fmaf(a, wls.x, s2a);  s2b = fmaf(a, wls.y, s2b);
            vxa = fmaf(wx, wlv.x, vxa); vxb = fmaf(wx, wlv.y, vxb);
            vya = fmaf(wy, wlv.x, vya); vyb = fmaf(wy, wlv.y, vyb);
            vza = fmaf(wz, wlv.x, vza); vzb = fmaf(wz, wlv.y, vzb);
            if (ITER > 0) {
                float si = stS[f];
                float ux = stVi[f], uy = stVi[64 + f], uz = stVi[128 + f];
                float2 ws = *(const float2*)&sks[f * 64 + go];
                float2 wv = *(const float2*)&skv[f * 64 + go];
                sca = fmaf(si, ws.x, sca);  scb = fmaf(si, ws.y, scb);
                ka0 = fmaf(ux, wv.x, ka0);  kb0 = fmaf(ux, wv.y, kb0);
                ka1 = fmaf(uy, wv.x, ka1);  kb1 = fmaf(uy, wv.y, kb1);
                ka2 = fmaf(uz, wv.x, ka2);  kb2 = fmaf(uz, wv.y, kb2);
            }
        }

        // ---- product basis ----
        const float* pb = pw + spec * 9 * FF + go;
        float2 p0 = *(const float2*)&pb[0],   p1 = *(const float2*)&pb[64];
        float2 p2 = *(const float2*)&pb[128], p3 = *(const float2*)&pb[192];
        float2 p4 = *(const float2*)&pb[256], p5 = *(const float2*)&pb[320];
        float2 p6 = *(const float2*)&pb[384], p7 = *(const float2*)&pb[448];
        float2 p8 = *(const float2*)&pb[512];

        float vva = vxa * vxa + vya * vya + vza * vza;
        float vvb = vxb * vxb + vyb * vyb + vzb * vzb;
        float sqa = s2a * s2a, sqb = s2b * s2b;
        float psa = p0.x * s2a + p1.x * sqa + p2.x * vva + p3.x * sqa * s2a + p4.x * s2a * vva;
        float psb = p0.y * s2b + p1.y * sqb + p2.y * vvb + p3.y * sqb * s2b + p4.y * s2b * vvb;
        float pca = p5.x + p6.x * s2a + p7.x * sqa + p8.x * vva;
        float pcb = p5.y + p6.y * s2b + p7.y * sqb + p8.y * vvb;

        __syncwarp();
        stA[go] = psa;             stA[go + 1] = psb;
        stV[go] = pca * vxa;       stV[go + 1] = pcb * vxb;
        stV[64 + go] = pca * vya;  stV[64 + go + 1] = pcb * vyb;
        stV[128 + go] = pca * vza; stV[128 + go + 1] = pcb * vzb;
        __syncwarp();

        // ---- second matvec pair (+ skip add) ----
        float sna = (ITER > 0) ? sca : 0.f, snb = (ITER > 0) ? scb : 0.f;
        float na0 = (ITER > 0) ? ka0 : 0.f, nb0 = (ITER > 0) ? kb0 : 0.f;
        float na1 = (ITER > 0) ? ka1 : 0.f, nb1 = (ITER > 0) ? kb1 : 0.f;
        float na2 = (ITER > 0) ? ka2 : 0.f, nb2 = (ITER > 0) ? kb2 : 0.f;
#pragma unroll 8
        for (int f = 0; f < FF; f++) {
            float a  = stA[f];
            float wx = stV[f], wy = stV[64 + f], wz = stV[128 + f];
            float2 wps = *(const float2*)&sWps[f * 64 + go];
            float2 wpv = *(const float2*)&sWpv[f * 64 + go];
            sna = fmaf(a, wps.x, sna);  snb = fmaf(a, wps.y, snb);
            na0 = fmaf(wx, wpv.x, na0); nb0 = fmaf(wx, wpv.y, nb0);
            na1 = fmaf(wy, wpv.x, na1); nb1 = fmaf(wy, wpv.y, nb1);
            na2 = fmaf(wz, wpv.x, na2); nb2 = fmaf(wz, wpv.y, nb2);
        }

        if (ITER == 0) {
            // next layer needs these
            *(float2*)&g_s1[n * FF + go] = make_float2(sna, snb);
            float* vo = g_v0 + n * 3 * FF;
            *(float2*)&vo[go]       = make_float2(na0, nb0);
            *(float2*)&vo[64 + go]  = make_float2(na1, nb1);
            *(float2*)&vo[128 + go] = make_float2(na2, nb2);

            // linear readout: warp shfl reduction
            float t = sna * Wread0[go] + snb * Wread0[go + 1];
#pragma unroll
            for (int o = 16; o > 0; o >>= 1)
                t += __shfl_xor_sync(0xffffffffu, t, o);
            if (g2 == 0) out[n * LL + 0] = t;
        } else {
            // nonlinear readout: stage s, 16 lanes do hidden layer
            __syncwarp();
            stA[go] = sna; stA[go + 1] = snb;
            __syncwarp();
            float t = 0.f;
            if (g2 < HH) {
                float h = 0.f;
#pragma unroll 8
                for (int f = 0; f < FF; f++)
                    h = fmaf(stA[f], Wr1a[f * HH + g2], h);
                h = h / (1.0f + expf(-h));  // silu
                t = h * Wr1b[g2];
            }
#pragma unroll
            for (int o = 16; o > 0; o >>= 1)
                t += __shfl_xor_sync(0xffffffffu, t, o);
            if (g2 == 0) out[n * LL + 1] = t;
        }
        __syncwarp();
    }
}

// ---------------- host launch -------------------------------------------------
extern "C" void kernel_launch(void* const* d_in, const int* in_sizes, int n_in,
                              void* d_out, int out_size)
{
    const float* vectors  = (const float*)d_in[0];
    const float* embed_s  = (const float*)d_in[1];
    const float* Wr       = (const float*)d_in[2];   // [2,8,320]
    const float* Wls      = (const float*)d_in[3];   // [2,64,64]
    const float* Wlv      = (const float*)d_in[4];
    const float* skip_s   = (const float*)d_in[5];   // [10,64,64]
    const float* skip_v   = (const float*)d_in[6];
    const float* pw       = (const float*)d_in[7];   // [2,10,9,64]
    const float* Wps      = (const float*)d_in[8];
    const float* Wpv      = (const float*)d_in[9];
    const float* Wread0   = (const float*)d_in[10];  // [64,1]
    const float* Wr1a     = (const float*)d_in[11];  // [64,16]
    const float* Wr1b     = (const float*)d_in[12];  // [16,1]
    const int*   senders  = (const int*)d_in[13];
    const int*   receivers= (const int*)d_in[14];
    const int*   species  = (const int*)d_in[15];
    float* out = (float*)d_out;

    static bool attr_done = false;
    if (!attr_done) {
        cudaFuncSetAttribute((const void*)node_kernel<0>,
                             cudaFuncAttributeMaxDynamicSharedMemorySize, SMEM_NODE);
        cudaFuncSetAttribute((const void*)node_kernel<1>,
                             cudaFuncAttributeMaxDynamicSharedMemorySize, SMEM_NODE);
        attr_done = true;
    }

    const int zblocks = (NN * FF + 255) / 256;

    precompute_kernel<<<EE / 256, 256>>>(vectors);
    init_kernel<<<(NN * FF) / 256, 256>>>(embed_s, species);

    // ---- layer 0 ----
    zero_agg_kernel<<<zblocks, 256>>>();
    edge_kernel<0><<<2048, 256>>>(Wr, senders, receivers);
    node_kernel<0><<<NN / 64, 256, SMEM_NODE>>>(
        species, Wls, Wlv, Wps, Wpv, skip_s, skip_v, pw,
        Wread0, Wr1a, Wr1b, out);

    // ---- layer 1 ----
    zero_agg_kernel<<<zblocks, 256>>>();
    edge_kernel<1><<<2048, 256>>>(Wr + NBB * 5 * FF, senders, receivers);
    node_kernel<1><<<NN / 64, 256, SMEM_NODE>>>(
        species,
        Wls + FF * FF, Wlv + FF * FF, Wps + FF * FF, Wpv + FF * FF,
        skip_s, skip_v, pw + ZZ * 9 * FF,
        Wread0, Wr1a, Wr1b, out);
}